// round 12
// baseline (speedup 1.0000x reference)
#include <cuda_runtime.h>
#include <cuda_fp16.h>
#include <cstdint>

// Problem constants
#define BB 2
#define TT 2048
#define DD 1024
#define HH 16
#define DHH 64
#define M_TOT (BB*TT)                 // 4096
#define PRESENT_HALF (BB*HH*TT*DHH)   // 4194304
#define PLANE ((size_t)BB*HH*TT*DHH)  // elements per hi/lo plane
#define GK 1024                       // GEMM K (compile-time)
#define NCH 64                        // GK/16 chunks

// ---------------------------------------------------------------------------
// Device-global scratch.
// B-operand layout (weights, hi+lo interleaved): row [K], K/16 chunks of 64B,
//   chunk = pairs [p0,p4,p1,p5,p2,p6,p3,p7], pair = 8B [hi2|lo2] fp16.
// A-operand layout (x, attn-out; hi only): row [K], K/16 chunks of 32B,
//   chunk = pairs [p0,p4,p1,p5,p2,p6,p3,p7], pair = 4B [hi(2k),hi(2k+1)].
// Attention planes: Q = [hi|lo], K/V = hi only. [B][H][T][64] fp16.
// ---------------------------------------------------------------------------
__device__ unsigned char g_xs[(size_t)M_TOT * DD * 2];
__device__ unsigned char g_bta[(size_t)3 * DD * DD * 4];
__device__ unsigned char g_btp[(size_t)DD * DD * 4];
__device__ __half g_qs[2 * PLANE];
__device__ __half g_ks[PLANE];
__device__ __half g_vs[PLANE];
__device__ unsigned char g_atts[(size_t)M_TOT * DD * 2];

// ---------------------------------------------------------------------------
// Helpers
// ---------------------------------------------------------------------------
__device__ __forceinline__ uint32_t smem_to_u32(const void* smem_ptr) {
    uint32_t addr;
    asm("{ .reg .u64 tmp; cvta.to.shared.u64 tmp, %1; cvt.u32.u64 %0, tmp; }"
        : "=r"(addr) : "l"(smem_ptr));
    return addr;
}

__device__ __forceinline__ uint32_t pack2h(float a, float b) {
    __half2 h = __floats2half2_rn(a, b);
    return *reinterpret_cast<uint32_t*>(&h);
}

__device__ __forceinline__ void split_pair(float a, float b,
                                           uint32_t& wh, uint32_t& wl) {
    __half ha = __float2half_rn(a);
    __half hb = __float2half_rn(b);
    float la = a - __half2float(ha);
    float lb = b - __half2float(hb);
    __half2 h = __halves2half2(ha, hb);
    __half2 l = __floats2half2_rn(la, lb);
    wh = *reinterpret_cast<uint32_t*>(&h);
    wl = *reinterpret_cast<uint32_t*>(&l);
}

__device__ __forceinline__ int pairoffB(int P) {
    int ch = P >> 3, p = P & 7;
    return ch * 64 + (p & 3) * 16 + (p >> 2) * 8;
}
__device__ __forceinline__ int pairoffA(int P) {
    int ch = P >> 3, p = P & 7;
    return ch * 32 + (p & 3) * 8 + (p >> 2) * 4;
}

__device__ __forceinline__ float fast_exp(float x) {
    x = fmaxf(x, -87.0f);
    float t = fmaf(x, 1.4426950408889634f, 12582912.0f);
    int   ni = __float_as_int(t);
    float n = t - 12582912.0f;
    float f = fmaf(x, 1.4426950408889634f, -n);
    float p = 1.3333558146e-3f;
    p = fmaf(p, f, 9.6181291076e-3f);
    p = fmaf(p, f, 5.5504108665e-2f);
    p = fmaf(p, f, 2.4022650696e-1f);
    p = fmaf(p, f, 6.9314718056e-1f);
    p = fmaf(p, f, 1.0f);
    return __int_as_float(__float_as_int(p) + (int)((unsigned)ni << 23));
}

#define CP16(s, g) \
    asm volatile("cp.async.cg.shared.global [%0], [%1], 16;" :: "r"(s), "l"(g))
#define CP_COMMIT() asm volatile("cp.async.commit_group;" ::: "memory")
#define CP_WAIT1()  asm volatile("cp.async.wait_group 1;" ::: "memory")
#define CP_WAIT2()  asm volatile("cp.async.wait_group 2;" ::: "memory")

#define MMA_F16(c, a, b) \
    asm volatile("mma.sync.aligned.m16n8k16.row.col.f32.f16.f16.f32 " \
        "{%0,%1,%2,%3},{%4,%5,%6,%7},{%8,%9},{%0,%1,%2,%3};" \
        : "+f"((c)[0]), "+f"((c)[1]), "+f"((c)[2]), "+f"((c)[3]) \
        : "r"((a)[0]), "r"((a)[1]), "r"((a)[2]), "r"((a)[3]), \
          "r"((b)[0]), "r"((b)[1]))

#define LDMX4(R, addr) \
    asm volatile("ldmatrix.sync.aligned.m8n8.x4.shared.b16 {%0,%1,%2,%3}, [%4];" \
        : "=r"((R)[0]), "=r"((R)[1]), "=r"((R)[2]), "=r"((R)[3]) : "r"(addr))

#define LDMX4T(R, addr) \
    asm volatile("ldmatrix.sync.aligned.m8n8.x4.trans.shared.b16 {%0,%1,%2,%3}, [%4];" \
        : "=r"((R)[0]), "=r"((R)[1]), "=r"((R)[2]), "=r"((R)[3]) : "r"(addr))

// ---------------------------------------------------------------------------
// Prepass 1: x -> hi-only interleaved A layout
// ---------------------------------------------------------------------------
__global__ void split_kernel(const float4* __restrict__ src,
                             unsigned char* __restrict__ dst, int n4)
{
    int i = blockIdx.x * blockDim.x + threadIdx.x;
    if (i < n4) {
        float4 v = src[i];
        int e = 4 * i;
        int row = e >> 10;
        int P0 = (e & 1023) >> 1;
        unsigned char* base = dst + (size_t)row * 2048;
        *(uint32_t*)(base + pairoffA(P0))     = pack2h(v.x, v.y);
        *(uint32_t*)(base + pairoffA(P0 + 1)) = pack2h(v.z, v.w);
    }
}

// ---------------------------------------------------------------------------
// Prepass 2: W[K,N] -> Bt[N][K] interleaved packed-split (hi+lo)
// ---------------------------------------------------------------------------
__global__ void transpose_split_kernel(const float* __restrict__ w,
                                       unsigned char* __restrict__ bt,
                                       int Kd, int Nd)
{
    __shared__ float t[32][33];
    int n0 = blockIdx.x * 32, k0 = blockIdx.y * 32;
    int tx = threadIdx.x, ty = threadIdx.y;
#pragma unroll
    for (int i = 0; i < 32; i += 8)
        t[ty + i][tx] = w[(size_t)(k0 + ty + i) * Nd + n0 + tx];
    __syncthreads();
    int tid = ty * 32 + tx;
    int po = tid & 15;
    int nl = tid >> 4;
#pragma unroll
    for (int half = 0; half < 2; half++) {
        int n_loc = nl + half * 16;
        float v0 = t[2 * po][n_loc];
        float v1 = t[2 * po + 1][n_loc];
        uint2 o;
        split_pair(v0, v1, o.x, o.y);
        *(uint2*)(bt + (size_t)(n0 + n_loc) * Kd * 4
                     + pairoffB((k0 >> 1) + po)) = o;
    }
}

// ---------------------------------------------------------------------------
// fp16 2-term mma.sync GEMM: C = Ahi @ (Bhi+Blo)^T + bias.  K = GK (1024).
// CTA 128x128, 256 thr. 8-stage pipeline, 2 chunks (32 k) per iteration:
// one __syncthreads per 64 MMAs. Prefetch pair -> stages (ch+6,ch+7)&7,
// disjoint from the stages being read (ch,ch+1)&7.
// ---------------------------------------------------------------------------
#define GSTAGE 12288
#define GSMEM  (8 * GSTAGE)   // 98304

__global__ __launch_bounds__(256, 2) void f16_gemm_kernel(
    const unsigned char* __restrict__ Ag, const unsigned char* __restrict__ Bg,
    const float* __restrict__ bias,
    float* __restrict__ Cout,
    __half* __restrict__ qsp, __half* __restrict__ ksp,
    __half* __restrict__ vsp,
    float* __restrict__ present, int N, int mode)
{
    extern __shared__ char smem[];
    const uint32_t smem_u = smem_to_u32(smem);
    const int tid = threadIdx.x;
    const int lane = tid & 31, wid = tid >> 5;
    const int wm = wid & 1, wn = wid >> 1;
    const int rowBase = blockIdx.y * 128, colBase = blockIdx.x * 128;

    const int ldr = tid >> 1;
    const unsigned char* gA = Ag + (size_t)(rowBase + ldr) * (GK * 2)
                                 + (tid & 1) * 16;
    const unsigned char* gB = Bg + (size_t)(colBase + ldr) * (GK * 4)
                                 + (tid & 1) * 32;
    const uint32_t sA = smem_u + ldr * 32 + (tid & 1) * 16;
    const uint32_t sB = smem_u + 4096 + ldr * 64 + (tid & 1) * 32;

#define LOAD_STAGE(chunk, stg) do {                        \
        uint32_t so = (uint32_t)(stg) * GSTAGE;            \
        CP16(sA + so,      gA + (size_t)(chunk) * 32);     \
        CP16(sB + so,      gB + (size_t)(chunk) * 64);     \
        CP16(sB + so + 16, gB + (size_t)(chunk) * 64 + 16);\
    } while (0)

    float c[4][4][4];
#pragma unroll
    for (int i = 0; i < 4; i++)
#pragma unroll
        for (int j = 0; j < 4; j++)
#pragma unroll
            for (int r = 0; r < 4; r++) c[i][j][r] = 0.0f;

    // Preload chunks 0..5 as 3 pair-groups
    LOAD_STAGE(0, 0); LOAD_STAGE(1, 1); CP_COMMIT();
    LOAD_STAGE(2, 2); LOAD_STAGE(3, 3); CP_COMMIT();
    LOAD_STAGE(4, 4); LOAD_STAGE(5, 5); CP_COMMIT();

    // per-thread invariant smem offsets
    const uint32_t aoff = (uint32_t)((wm * 64 + (lane >> 2)) * 32
                                     + (lane & 3) * 8);
    const uint32_t boff = (uint32_t)(4096 + (wn * 32 + (lane >> 2)) * 64
                                     + (lane & 3) * 16);
    const char* smem_c = smem;

#define GEMM_FRAGS(sbase, ah, bh, bl) do {                                  \
        _Pragma("unroll")                                                   \
        for (int mf = 0; mf < 4; mf++) {                                    \
            const char* p = smem_c + aoff + (sbase) + mf * 512;             \
            uint2 t0 = *(const uint2*)(p);                                  \
            uint2 t1 = *(const uint2*)(p + 256);                            \
            ah[mf][0] = t0.x; ah[mf][2] = t0.y;                             \
            ah[mf][1] = t1.x; ah[mf][3] = t1.y;                             \
        }                                                                   \
        _Pragma("unroll")                                                   \
        for (int nf = 0; nf < 4; nf++) {                                    \
            uint4 V = *(const uint4*)(smem_c + boff + (sbase) + nf * 512);  \
            bh[nf][0] = V.x; bl[nf][0] = V.y;                               \
            bh[nf][1] = V.z; bl[nf][1] = V.w;                               \
        }                                                                   \
    } while (0)

#define GEMM_MMAS(ah, bh, bl) do {                                         \
        _Pragma("unroll")                                                   \
        for (int mf = 0; mf < 4; mf++)                                      \
            _Pragma("unroll")                                               \
            for (int nf = 0; nf < 4; nf++)                                  \
                MMA_F16(c[mf][nf], ah[mf], bh[nf]);                         \
        _Pragma("unroll")                                                   \
        for (int mf = 0; mf < 4; mf++)                                      \
            _Pragma("unroll")                                               \
            for (int nf = 0; nf < 4; nf++)                                  \
                MMA_F16(c[mf][nf], ah[mf], bl[nf]);                         \
    } while (0)

#pragma unroll 4
    for (int ch = 0; ch < NCH; ch += 2) {
        CP_WAIT2();
        __syncthreads();
        const uint32_t sb0 = (uint32_t)((ch & 7) * GSTAGE);
        const uint32_t sb1 = (uint32_t)(((ch + 1) & 7) * GSTAGE);

        uint32_t ah[4][4], bh[4][2], bl[4][2];
        GEMM_FRAGS(sb0, ah, bh, bl);

        // prefetch pair (ch+6, ch+7) into stages (ch+6)&7,(ch+7)&7
        if (ch + 6 < NCH) {
            LOAD_STAGE(ch + 6, (ch + 6) & 7);
            LOAD_STAGE(ch + 7, (ch + 7) & 7);
        }
        CP_COMMIT();

        GEMM_MMAS(ah, bh, bl);

        GEMM_FRAGS(sb1, ah, bh, bl);
        GEMM_MMAS(ah, bh, bl);
    }

    // Epilogue
#pragma unroll
    for (int mf = 0; mf < 4; mf++) {
#pragma unroll
        for (int nf = 0; nf < 4; nf++) {
            int m0 = rowBase + wm * 64 + mf * 16 + (lane >> 2);
            int n  = colBase + wn * 32 + nf * 8 + (lane & 3) * 2;
            float b0 = bias[n], b1 = bias[n + 1];
#pragma unroll
            for (int half = 0; half < 2; half++) {
                int m = m0 + half * 8;
                float2 v;
                v.x = c[mf][nf][half * 2 + 0] + b0;
                v.y = c[mf][nf][half * 2 + 1] + b1;
                if (mode == 1) {
                    *(float2*)&Cout[(size_t)m * N + n] = v;
                } else {
                    int seg = n >> 10, nn = n & 1023;
                    int hh = nn >> 6, d = nn & 63;
                    int bb = m >> 11, t = m & 2047;
                    size_t idx = (((size_t)(bb * HH + hh)) * TT + t) * DHH + d;
                    if (seg == 0) {
                        uint32_t wh, wl;
                        split_pair(v.x, v.y, wh, wl);
                        *(uint32_t*)&qsp[idx] = wh;
                        *(uint32_t*)&qsp[PLANE + idx] = wl;
                    } else if (seg == 1) {
                        *(float2*)&present[idx] = v;
                        *(uint32_t*)&ksp[idx] = pack2h(v.x, v.y);
                    } else {
                        *(float2*)&present[PRESENT_HALF + idx] = v;
                        *(uint32_t*)&vsp[idx] = pack2h(v.x, v.y);
                    }
                }
            }
        }
    }
}

// ---------------------------------------------------------------------------
// Flash attention on tensor cores (fp16, 2-term Q/P vs hi-only K/V).
// Block: 128 q-rows x 64 k-cols, 8 warps, reversed qt. kt loop manually
// unrolled x2 so stage addressing constant-folds (ntiles always even).
// ---------------------------------------------------------------------------
#define ASTRIDE 144
#define ABYTES  (64 * ASTRIDE)
#define QBYTES  (128 * ASTRIDE)
#define ATT_SMEM (2 * QBYTES + 2 * 2 * ABYTES)   // 73728

__device__ __forceinline__ void att_load_stage(
    uint32_t dst, const __half* kh_g, const __half* vh_g, int k0, int tid)
{
    int r = tid >> 2;
    int qo = (tid & 3) * 32;
    const char* skh = (const char*)(kh_g + (size_t)(k0 + r) * DHH) + qo;
    const char* svh = (const char*)(vh_g + (size_t)(k0 + r) * DHH) + qo;
    uint32_t d0 = dst + r * ASTRIDE + qo;
#pragma unroll
    for (int i = 0; i < 2; i++) {
        CP16(d0 + i * 16,          skh + i * 16);
        CP16(d0 + ABYTES + i * 16, svh + i * 16);
    }
}

__global__ __launch_bounds__(256) void attn_mma_kernel(
    const __half* __restrict__ qs, const __half* __restrict__ ks,
    const __half* __restrict__ vs, unsigned char* __restrict__ atts)
{
    extern __shared__ char sm[];
    const uint32_t su = smem_to_u32(sm);
    const int tid = threadIdx.x, lane = tid & 31, w = tid >> 5;
    const int qt = gridDim.x - 1 - blockIdx.x;
    const int h = blockIdx.y, b = blockIdx.z;
    const int q0 = qt * 128;
    const size_t headoff = ((size_t)(b * HH + h)) * TT * DHH;

    const uint32_t sQh = su;
    const uint32_t sQl = su + QBYTES;
    const uint32_t sStg = su + 2 * QBYTES;

    const __half* qh_g = qs + headoff;
    const __half* ql_g = qs + PLANE + headoff;
    const __half* kh_g = ks + headoff;
    const __half* vh_g = vs + headoff;

    // preload Q (hi+lo, 128 rows) + stage 0
    {
        int r = tid >> 1;
        int cb = (tid & 1) * 64;
        const char* sh = (const char*)(qh_g + (size_t)(q0 + r) * DHH) + cb;
        const char* sl = (const char*)(ql_g + (size_t)(q0 + r) * DHH) + cb;
        uint32_t dh_ = sQh + r * ASTRIDE + cb;
        uint32_t dl_ = sQl + r * ASTRIDE + cb;
#pragma unroll
        for (int i = 0; i < 4; i++) {
            CP16(dh_ + i * 16, sh + i * 16);
            CP16(dl_ + i * 16, sl + i * 16);
        }
        att_load_stage(sStg, kh_g, vh_g, 0, tid);
    }
    CP_COMMIT();

    uint32_t qfh[4][4], qfl[4][4];
    float co[8][4];
#pragma unroll
    for (int j = 0; j < 8; j++)
#pragma unroll
        for (int e = 0; e < 4; e++) co[j][e] = 0.0f;
    float mi[2] = {-1e30f, -1e30f}, li[2] = {0.0f, 0.0f};

    const int r0 = lane >> 2;
    const int cbase = 2 * (lane & 3);
    const int ntiles = 2 * qt + 2;   // always even
    const int wrow = q0 + (w << 4);

    auto tile_body = [&](int kt, uint32_t bKh, uint32_t ldst) {
        const int k0 = kt * 64;
        if (kt + 1 < ntiles)
            att_load_stage(ldst, kh_g, vh_g, (kt + 1) * 64, tid);
        CP_COMMIT();
        CP_WAIT1();
        __syncthreads();

        if (kt == 0) {
            int row = (w << 4) + (lane & 15);
            int colb = ((lane >> 4) << 3);
#pragma unroll
            for (int t = 0; t < 4; t++) {
                LDMX4(qfh[t], sQh + row * ASTRIDE + (t * 16 + colb) * 2);
                LDMX4(qfl[t], sQl + row * ASTRIDE + (t * 16 + colb) * 2);
            }
        }

        const bool active = (k0 <= wrow + 15);
        if (active) {
            const uint32_t bVh = bKh + ABYTES;

            // ---- S = (Qh+Ql) Kh^T : fragment-batched ----
            float cs[8][4];
#pragma unroll
            for (int j = 0; j < 8; j++)
#pragma unroll
                for (int e = 0; e < 4; e++) cs[j][e] = 0.0f;

#pragma unroll
            for (int u = 0; u < 2; u++) {
                uint32_t kf[8][4];
                int cola = u * 32 + ((lane >> 3) << 3);
#pragma unroll
                for (int j = 0; j < 8; j++) {
                    int rowa = j * 8 + (lane & 7);
                    LDMX4(kf[j], bKh + rowa * ASTRIDE + cola * 2);
                }
#pragma unroll
                for (int j = 0; j < 8; j++) MMA_F16(cs[j], qfh[2 * u], kf[j]);
#pragma unroll
                for (int j = 0; j < 8; j++) MMA_F16(cs[j], qfl[2 * u], kf[j]);
#pragma unroll
                for (int j = 0; j < 8; j++) MMA_F16(cs[j], qfh[2 * u + 1], kf[j] + 2);
#pragma unroll
                for (int j = 0; j < 8; j++) MMA_F16(cs[j], qfl[2 * u + 1], kf[j] + 2);
            }

            // ---- scale + causal mask ----
            if (k0 + 63 >= wrow) {
#pragma unroll
                for (int j = 0; j < 8; j++)
#pragma unroll
                    for (int e = 0; e < 4; e++) {
                        int gcol = k0 + j * 8 + cbase + (e & 1);
                        int grow = wrow + r0 + 8 * (e >> 1);
                        float sv = cs[j][e] * 0.25f;
                        cs[j][e] = (gcol > grow) ? -1e30f : sv;
                    }
            } else {
#pragma unroll
                for (int j = 0; j < 8; j++)
#pragma unroll
                    for (int e = 0; e < 4; e++) cs[j][e] *= 0.25f;
            }

            // ---- online softmax ----
#pragma unroll
            for (int half = 0; half < 2; half++) {
                float mx = -1e30f;
#pragma unroll
                for (int j = 0; j < 8; j++)
                    mx = fmaxf(mx, fmaxf(cs[j][2 * half], cs[j][2 * half + 1]));
                mx = fmaxf(mx, __shfl_xor_sync(0xffffffffu, mx, 1));
                mx = fmaxf(mx, __shfl_xor_sync(0xffffffffu, mx, 2));
                float mn = fmaxf(mi[half], mx);
                float alpha = fast_exp(mi[half] - mn);
                mi[half] = mn;
                float rs = 0.0f;
#pragma unroll
                for (int j = 0; j < 8; j++) {
                    float p0 = fast_exp(cs[j][2 * half]     - mn);
                    float p1 = fast_exp(cs[j][2 * half + 1] - mn);
                    cs[j][2 * half] = p0;
                    cs[j][2 * half + 1] = p1;
                    rs += p0 + p1;
                }
                rs += __shfl_xor_sync(0xffffffffu, rs, 1);
                rs += __shfl_xor_sync(0xffffffffu, rs, 2);
                li[half] = li[half] * alpha + rs;
#pragma unroll
                for (int j = 0; j < 8; j++) {
                    co[j][2 * half]     *= alpha;
                    co[j][2 * half + 1] *= alpha;
                }
            }

            // ---- pack P (hi/lo) ----
            uint32_t pfh[4][4], pfl[4][4];
#pragma unroll
            for (int t = 0; t < 4; t++)
#pragma unroll
                for (int sub = 0; sub < 2; sub++) {
                    int j = 2 * t + sub;
                    split_pair(cs[j][0], cs[j][1],
                               pfh[t][sub * 2 + 0], pfl[t][sub * 2 + 0]);
                    split_pair(cs[j][2], cs[j][3],
                               pfh[t][sub * 2 + 1], pfl[t][sub * 2 + 1]);
                }

            // ---- O += (Ph+Pl) Vh : fragment-batched ----
#pragma unroll
            for (int t = 0; t < 4; t++) {
                uint32_t vf[4][4];
                int rowv = t * 16 + (lane & 7) + ((lane >> 3) & 1) * 8;
#pragma unroll
                for (int np = 0; np < 4; np++) {
                    int colv = np * 16 + ((lane >> 4) << 3);
                    LDMX4T(vf[np], bVh + rowv * ASTRIDE + colv * 2);
                }
#pragma unroll
                for (int np = 0; np < 4; np++) {
                    MMA_F16(co[2 * np],     pfh[t], vf[np]);
                    MMA_F16(co[2 * np + 1], pfh[t], vf[np] + 2);
                }
#pragma unroll
                for (int np = 0; np < 4; np++) {
                    MMA_F16(co[2 * np],     pfl[t], vf[np]);
                    MMA_F16(co[2 * np + 1], pfl[t], vf[np] + 2);
                }
            }
        }
        __syncthreads();
    };

    const uint32_t st0 = sStg;
    const uint32_t st1 = sStg + 2 * ABYTES;
    for (int kt = 0; kt < ntiles; kt += 2) {
        tile_body(kt,     st0, st1);
        tile_body(kt + 1, st1, st0);
    }

    // ---- epilogue: normalize, write hi-only A layout for proj ----
    float inv0 = 1.0f / li[0], inv1 = 1.0f / li[1];
#pragma unroll
    for (int j = 0; j < 8; j++) {
#pragma unroll
        for (int half = 0; half < 2; half++) {
            float inv = half ? inv1 : inv0;
            int row = (w << 4) + r0 + 8 * half;
            int m = b * TT + q0 + row;
            int Pidx = h * 32 + j * 4 + (lane & 3);
            *(uint32_t*)(atts + (size_t)m * 2048 + pairoffA(Pidx)) =
                pack2h(co[j][2 * half] * inv, co[j][2 * half + 1] * inv);
        }
    }
}

// ---------------------------------------------------------------------------
extern "C" void kernel_launch(void* const* d_in, const int* in_sizes, int n_in,
                              void* d_out, int out_size)
{
    const float* x      = (const float*)d_in[0];
    const float* w_attn = (const float*)d_in[1];
    const float* b_attn = (const float*)d_in[2];
    const float* w_proj = (const float*)d_in[3];
    const float* b_proj = (const float*)d_in[4];

    float* out = (float*)d_out;
    float* a_out = out;
    float* present = out + (size_t)M_TOT * DD;

    unsigned char *xs, *bta, *btp, *atts;
    __half *qsp, *ksp, *vsp;
    cudaGetSymbolAddress((void**)&xs,   g_xs);
    cudaGetSymbolAddress((void**)&bta,  g_bta);
    cudaGetSymbolAddress((void**)&btp,  g_btp);
    cudaGetSymbolAddress((void**)&atts, g_atts);
    cudaGetSymbolAddress((void**)&qsp,  g_qs);
    cudaGetSymbolAddress((void**)&ksp,  g_ks);
    cudaGetSymbolAddress((void**)&vsp,  g_vs);

    cudaFuncSetAttribute(f16_gemm_kernel,
                         cudaFuncAttributeMaxDynamicSharedMemorySize, GSMEM);
    cudaFuncSetAttribute(attn_mma_kernel,
                         cudaFuncAttributeMaxDynamicSharedMemorySize, ATT_SMEM);

    // Prepasses
    split_kernel<<<(M_TOT * DD / 4 + 255) / 256, 256>>>(
        (const float4*)x, xs, M_TOT * DD / 4);
    transpose_split_kernel<<<dim3(3 * DD / 32, DD / 32), dim3(32, 8)>>>(
        w_attn, bta, DD, 3 * DD);
    transpose_split_kernel<<<dim3(DD / 32, DD / 32), dim3(32, 8)>>>(
        w_proj, btp, DD, DD);

    // QKV GEMM (2-term) -> q hi/lo, k/v hi + fp32 present
    f16_gemm_kernel<<<dim3(3 * DD / 128, M_TOT / 128), 256, GSMEM>>>(
        xs, bta, b_attn, nullptr, qsp, ksp, vsp, present, 3 * DD, 0);

    // Tensor-core flash attention (2-term) -> g_atts (hi-only)
    attn_mma_kernel<<<dim3(TT / 128, HH, BB), 256, ATT_SMEM>>>(
        qsp, ksp, vsp, atts);

    // Projection GEMM (2-term) -> a_out
    f16_gemm_kernel<<<dim3(DD / 128, M_TOT / 128), 256, GSMEM>>>(
        atts, btp, b_proj, a_out, nullptr, nullptr, nullptr, nullptr, DD, 1);
}

// round 13
// speedup vs baseline: 1.1110x; 1.1110x over previous
#include <cuda_runtime.h>
#include <cuda_fp16.h>
#include <cstdint>

// Problem constants
#define BB 2
#define TT 2048
#define DD 1024
#define HH 16
#define DHH 64
#define M_TOT (BB*TT)                 // 4096
#define PRESENT_HALF (BB*HH*TT*DHH)   // 4194304
#define PLANE ((size_t)BB*HH*TT*DHH)  // elements per plane
#define GK 1024                       // GEMM K (compile-time)
#define NCH 64                        // GK/16 chunks

// ---------------------------------------------------------------------------
// Device-global scratch.
// B-operand layout (weights, hi+lo interleaved): row [K], K/16 chunks of 64B,
//   chunk = pairs [p0,p4,p1,p5,p2,p6,p3,p7], pair = 8B [hi2|lo2] fp16.
// A-operand layout (x, attn-out; hi only): row [K], K/16 chunks of 32B.
// Attention planes: Q/K/V all hi-only. [B][H][T][64] fp16.
// ---------------------------------------------------------------------------
__device__ unsigned char g_xs[(size_t)M_TOT * DD * 2];
__device__ unsigned char g_bta[(size_t)3 * DD * DD * 4];
__device__ unsigned char g_btp[(size_t)DD * DD * 4];
__device__ __half g_qs[PLANE];
__device__ __half g_ks[PLANE];
__device__ __half g_vs[PLANE];
__device__ unsigned char g_atts[(size_t)M_TOT * DD * 2];

// ---------------------------------------------------------------------------
// Helpers
// ---------------------------------------------------------------------------
__device__ __forceinline__ uint32_t smem_to_u32(const void* smem_ptr) {
    uint32_t addr;
    asm("{ .reg .u64 tmp; cvta.to.shared.u64 tmp, %1; cvt.u32.u64 %0, tmp; }"
        : "=r"(addr) : "l"(smem_ptr));
    return addr;
}

__device__ __forceinline__ uint32_t pack2h(float a, float b) {
    __half2 h = __floats2half2_rn(a, b);
    return *reinterpret_cast<uint32_t*>(&h);
}

__device__ __forceinline__ void split_pair(float a, float b,
                                           uint32_t& wh, uint32_t& wl) {
    __half ha = __float2half_rn(a);
    __half hb = __float2half_rn(b);
    float la = a - __half2float(ha);
    float lb = b - __half2float(hb);
    __half2 h = __halves2half2(ha, hb);
    __half2 l = __floats2half2_rn(la, lb);
    wh = *reinterpret_cast<uint32_t*>(&h);
    wl = *reinterpret_cast<uint32_t*>(&l);
}

__device__ __forceinline__ int pairoffB(int P) {
    int ch = P >> 3, p = P & 7;
    return ch * 64 + (p & 3) * 16 + (p >> 2) * 8;
}
__device__ __forceinline__ int pairoffA(int P) {
    int ch = P >> 3, p = P & 7;
    return ch * 32 + (p & 3) * 8 + (p >> 2) * 4;
}

__device__ __forceinline__ float fast_exp(float x) {
    x = fmaxf(x, -87.0f);
    float t = fmaf(x, 1.4426950408889634f, 12582912.0f);
    int   ni = __float_as_int(t);
    float n = t - 12582912.0f;
    float f = fmaf(x, 1.4426950408889634f, -n);
    float p = 1.3333558146e-3f;
    p = fmaf(p, f, 9.6181291076e-3f);
    p = fmaf(p, f, 5.5504108665e-2f);
    p = fmaf(p, f, 2.4022650696e-1f);
    p = fmaf(p, f, 6.9314718056e-1f);
    p = fmaf(p, f, 1.0f);
    return __int_as_float(__float_as_int(p) + (int)((unsigned)ni << 23));
}

#define CP16(s, g) \
    asm volatile("cp.async.cg.shared.global [%0], [%1], 16;" :: "r"(s), "l"(g))
#define CP_COMMIT() asm volatile("cp.async.commit_group;" ::: "memory")
#define CP_WAIT1()  asm volatile("cp.async.wait_group 1;" ::: "memory")
#define CP_WAIT2()  asm volatile("cp.async.wait_group 2;" ::: "memory")

#define MMA_F16(c, a, b) \
    asm volatile("mma.sync.aligned.m16n8k16.row.col.f32.f16.f16.f32 " \
        "{%0,%1,%2,%3},{%4,%5,%6,%7},{%8,%9},{%0,%1,%2,%3};" \
        : "+f"((c)[0]), "+f"((c)[1]), "+f"((c)[2]), "+f"((c)[3]) \
        : "r"((a)[0]), "r"((a)[1]), "r"((a)[2]), "r"((a)[3]), \
          "r"((b)[0]), "r"((b)[1]))

#define LDMX4(R, addr) \
    asm volatile("ldmatrix.sync.aligned.m8n8.x4.shared.b16 {%0,%1,%2,%3}, [%4];" \
        : "=r"((R)[0]), "=r"((R)[1]), "=r"((R)[2]), "=r"((R)[3]) : "r"(addr))

#define LDMX4T(R, addr) \
    asm volatile("ldmatrix.sync.aligned.m8n8.x4.trans.shared.b16 {%0,%1,%2,%3}, [%4];" \
        : "=r"((R)[0]), "=r"((R)[1]), "=r"((R)[2]), "=r"((R)[3]) : "r"(addr))

// ---------------------------------------------------------------------------
// Prepass 1: x -> hi-only interleaved A layout
// ---------------------------------------------------------------------------
__global__ void split_kernel(const float4* __restrict__ src,
                             unsigned char* __restrict__ dst, int n4)
{
    int i = blockIdx.x * blockDim.x + threadIdx.x;
    if (i < n4) {
        float4 v = src[i];
        int e = 4 * i;
        int row = e >> 10;
        int P0 = (e & 1023) >> 1;
        unsigned char* base = dst + (size_t)row * 2048;
        *(uint32_t*)(base + pairoffA(P0))     = pack2h(v.x, v.y);
        *(uint32_t*)(base + pairoffA(P0 + 1)) = pack2h(v.z, v.w);
    }
}

// ---------------------------------------------------------------------------
// Prepass 2: W[K,N] -> Bt[N][K] interleaved packed-split (hi+lo)
// ---------------------------------------------------------------------------
__global__ void transpose_split_kernel(const float* __restrict__ w,
                                       unsigned char* __restrict__ bt,
                                       int Kd, int Nd)
{
    __shared__ float t[32][33];
    int n0 = blockIdx.x * 32, k0 = blockIdx.y * 32;
    int tx = threadIdx.x, ty = threadIdx.y;
#pragma unroll
    for (int i = 0; i < 32; i += 8)
        t[ty + i][tx] = w[(size_t)(k0 + ty + i) * Nd + n0 + tx];
    __syncthreads();
    int tid = ty * 32 + tx;
    int po = tid & 15;
    int nl = tid >> 4;
#pragma unroll
    for (int half = 0; half < 2; half++) {
        int n_loc = nl + half * 16;
        float v0 = t[2 * po][n_loc];
        float v1 = t[2 * po + 1][n_loc];
        uint2 o;
        split_pair(v0, v1, o.x, o.y);
        *(uint2*)(bt + (size_t)(n0 + n_loc) * Kd * 4
                     + pairoffB((k0 >> 1) + po)) = o;
    }
}

// ---------------------------------------------------------------------------
// fp16 2-term mma.sync GEMM: C = Ahi @ (Bhi+Blo)^T + bias.  (R11 config.)
// CTA 128x128, 256 thr, chunk 16k, 4-stage, unroll 4.
// ---------------------------------------------------------------------------
#define GSTAGE 12288
#define GSMEM  (4 * GSTAGE)

__global__ __launch_bounds__(256, 2) void f16_gemm_kernel(
    const unsigned char* __restrict__ Ag, const unsigned char* __restrict__ Bg,
    const float* __restrict__ bias,
    float* __restrict__ Cout,
    __half* __restrict__ qsp, __half* __restrict__ ksp,
    __half* __restrict__ vsp,
    float* __restrict__ present, int N, int mode)
{
    extern __shared__ char smem[];
    const uint32_t smem_u = smem_to_u32(smem);
    const int tid = threadIdx.x;
    const int lane = tid & 31, wid = tid >> 5;
    const int wm = wid & 1, wn = wid >> 1;
    const int rowBase = blockIdx.y * 128, colBase = blockIdx.x * 128;

    const int ldr = tid >> 1;
    const unsigned char* gA = Ag + (size_t)(rowBase + ldr) * (GK * 2)
                                 + (tid & 1) * 16;
    const unsigned char* gB = Bg + (size_t)(colBase + ldr) * (GK * 4)
                                 + (tid & 1) * 32;
    const uint32_t sA = smem_u + ldr * 32 + (tid & 1) * 16;
    const uint32_t sB = smem_u + 4096 + ldr * 64 + (tid & 1) * 32;

#define LOAD_STAGE(chunk, stg) do {                        \
        uint32_t so = (uint32_t)(stg) * GSTAGE;            \
        CP16(sA + so,      gA + (size_t)(chunk) * 32);     \
        CP16(sB + so,      gB + (size_t)(chunk) * 64);     \
        CP16(sB + so + 16, gB + (size_t)(chunk) * 64 + 16);\
    } while (0)

    float c[4][4][4];
#pragma unroll
    for (int i = 0; i < 4; i++)
#pragma unroll
        for (int j = 0; j < 4; j++)
#pragma unroll
            for (int r = 0; r < 4; r++) c[i][j][r] = 0.0f;

    LOAD_STAGE(0, 0); CP_COMMIT();
    LOAD_STAGE(1, 1); CP_COMMIT();
    LOAD_STAGE(2, 2); CP_COMMIT();

    // per-thread invariant smem offsets
    const uint32_t aoff = (uint32_t)((wm * 64 + (lane >> 2)) * 32
                                     + (lane & 3) * 8);
    const uint32_t boff = (uint32_t)(4096 + (wn * 32 + (lane >> 2)) * 64
                                     + (lane & 3) * 16);

    const char* smem_c = smem;
#pragma unroll 4
    for (int ch = 0; ch < NCH; ch++) {
        CP_WAIT2();
        __syncthreads();
        const uint32_t sbase = (uint32_t)((ch & 3) * GSTAGE);

        uint32_t ah[4][4];
#pragma unroll
        for (int mf = 0; mf < 4; mf++) {
            const char* p = smem_c + aoff + sbase + mf * 512;
            uint2 t0 = *(const uint2*)(p);
            uint2 t1 = *(const uint2*)(p + 256);
            ah[mf][0] = t0.x; ah[mf][2] = t0.y;
            ah[mf][1] = t1.x; ah[mf][3] = t1.y;
        }
        uint32_t bh[4][2], bl[4][2];
#pragma unroll
        for (int nf = 0; nf < 4; nf++) {
            uint4 V = *(const uint4*)(smem_c + boff + sbase + nf * 512);
            bh[nf][0] = V.x; bl[nf][0] = V.y;
            bh[nf][1] = V.z; bl[nf][1] = V.w;
        }
        // term-major: accumulator revisit distance = 16 MMAs
#pragma unroll
        for (int mf = 0; mf < 4; mf++)
#pragma unroll
            for (int nf = 0; nf < 4; nf++)
                MMA_F16(c[mf][nf], ah[mf], bh[nf]);
#pragma unroll
        for (int mf = 0; mf < 4; mf++)
#pragma unroll
            for (int nf = 0; nf < 4; nf++)
                MMA_F16(c[mf][nf], ah[mf], bl[nf]);
        __syncthreads();
        if (ch + 3 < NCH) LOAD_STAGE(ch + 3, (ch + 3) & 3);
        CP_COMMIT();
    }

    // Epilogue
#pragma unroll
    for (int mf = 0; mf < 4; mf++) {
#pragma unroll
        for (int nf = 0; nf < 4; nf++) {
            int m0 = rowBase + wm * 64 + mf * 16 + (lane >> 2);
            int n  = colBase + wn * 32 + nf * 8 + (lane & 3) * 2;
            float b0 = bias[n], b1 = bias[n + 1];
#pragma unroll
            for (int half = 0; half < 2; half++) {
                int m = m0 + half * 8;
                float2 v;
                v.x = c[mf][nf][half * 2 + 0] + b0;
                v.y = c[mf][nf][half * 2 + 1] + b1;
                if (mode == 1) {
                    *(float2*)&Cout[(size_t)m * N + n] = v;
                } else {
                    int seg = n >> 10, nn = n & 1023;
                    int hh = nn >> 6, d = nn & 63;
                    int bb = m >> 11, t = m & 2047;
                    size_t idx = (((size_t)(bb * HH + hh)) * TT + t) * DHH + d;
                    if (seg == 0) {
                        *(uint32_t*)&qsp[idx] = pack2h(v.x, v.y);
                    } else if (seg == 1) {
                        *(float2*)&present[idx] = v;
                        *(uint32_t*)&ksp[idx] = pack2h(v.x, v.y);
                    } else {
                        *(float2*)&present[PRESENT_HALF + idx] = v;
                        *(uint32_t*)&vsp[idx] = pack2h(v.x, v.y);
                    }
                }
            }
        }
    }
}

// ---------------------------------------------------------------------------
// Flash attention on tensor cores (fp16).
// S = Qh Kh^T (1-term), O += (Ph+Pl) Vh (2-term on P side).
// Block: 128 q-rows x 64 k-cols, 8 warps, reversed qt. kt loop manually
// unrolled x2 so stage addressing constant-folds (ntiles always even).
// ---------------------------------------------------------------------------
#define ASTRIDE 144
#define ABYTES  (64 * ASTRIDE)
#define QBYTES  (128 * ASTRIDE)
#define ATT_SMEM (QBYTES + 2 * 2 * ABYTES)   // 55296

__device__ __forceinline__ void att_load_stage(
    uint32_t dst, const __half* kh_g, const __half* vh_g, int k0, int tid)
{
    int r = tid >> 2;
    int qo = (tid & 3) * 32;
    const char* skh = (const char*)(kh_g + (size_t)(k0 + r) * DHH) + qo;
    const char* svh = (const char*)(vh_g + (size_t)(k0 + r) * DHH) + qo;
    uint32_t d0 = dst + r * ASTRIDE + qo;
#pragma unroll
    for (int i = 0; i < 2; i++) {
        CP16(d0 + i * 16,          skh + i * 16);
        CP16(d0 + ABYTES + i * 16, svh + i * 16);
    }
}

__global__ __launch_bounds__(256) void attn_mma_kernel(
    const __half* __restrict__ qs, const __half* __restrict__ ks,
    const __half* __restrict__ vs, unsigned char* __restrict__ atts)
{
    extern __shared__ char sm[];
    const uint32_t su = smem_to_u32(sm);
    const int tid = threadIdx.x, lane = tid & 31, w = tid >> 5;
    const int qt = gridDim.x - 1 - blockIdx.x;
    const int h = blockIdx.y, b = blockIdx.z;
    const int q0 = qt * 128;
    const size_t headoff = ((size_t)(b * HH + h)) * TT * DHH;

    const uint32_t sQh = su;
    const uint32_t sStg = su + QBYTES;

    const __half* qh_g = qs + headoff;
    const __half* kh_g = ks + headoff;
    const __half* vh_g = vs + headoff;

    // preload Q (hi, 128 rows) + stage 0
    {
        int r = tid >> 1;
        int cb = (tid & 1) * 64;
        const char* sh = (const char*)(qh_g + (size_t)(q0 + r) * DHH) + cb;
        uint32_t dh_ = sQh + r * ASTRIDE + cb;
#pragma unroll
        for (int i = 0; i < 4; i++)
            CP16(dh_ + i * 16, sh + i * 16);
        att_load_stage(sStg, kh_g, vh_g, 0, tid);
    }
    CP_COMMIT();

    uint32_t qfh[4][4];
    float co[8][4];
#pragma unroll
    for (int j = 0; j < 8; j++)
#pragma unroll
        for (int e = 0; e < 4; e++) co[j][e] = 0.0f;
    float mi[2] = {-1e30f, -1e30f}, li[2] = {0.0f, 0.0f};

    const int r0 = lane >> 2;
    const int cbase = 2 * (lane & 3);
    const int ntiles = 2 * qt + 2;   // always even
    const int wrow = q0 + (w << 4);

    auto tile_body = [&](int kt, uint32_t bKh, uint32_t ldst) {
        const int k0 = kt * 64;
        if (kt + 1 < ntiles)
            att_load_stage(ldst, kh_g, vh_g, (kt + 1) * 64, tid);
        CP_COMMIT();
        CP_WAIT1();
        __syncthreads();

        if (kt == 0) {
            int row = (w << 4) + (lane & 15);
            int colb = ((lane >> 4) << 3);
#pragma unroll
            for (int t = 0; t < 4; t++)
                LDMX4(qfh[t], sQh + row * ASTRIDE + (t * 16 + colb) * 2);
        }

        const bool active = (k0 <= wrow + 15);
        if (active) {
            const uint32_t bVh = bKh + ABYTES;

            // ---- S = Qh Kh^T (1-term), fragment-batched ----
            float cs[8][4];
#pragma unroll
            for (int j = 0; j < 8; j++)
#pragma unroll
                for (int e = 0; e < 4; e++) cs[j][e] = 0.0f;

#pragma unroll
            for (int u = 0; u < 2; u++) {
                uint32_t kf[8][4];
                int cola = u * 32 + ((lane >> 3) << 3);
#pragma unroll
                for (int j = 0; j < 8; j++) {
                    int rowa = j * 8 + (lane & 7);
                    LDMX4(kf[j], bKh + rowa * ASTRIDE + cola * 2);
                }
#pragma unroll
                for (int j = 0; j < 8; j++) MMA_F16(cs[j], qfh[2 * u], kf[j]);
#pragma unroll
                for (int j = 0; j < 8; j++) MMA_F16(cs[j], qfh[2 * u + 1], kf[j] + 2);
            }

            // ---- scale + causal mask ----
            if (k0 + 63 >= wrow) {
#pragma unroll
                for (int j = 0; j < 8; j++)
#pragma unroll
                    for (int e = 0; e < 4; e++) {
                        int gcol = k0 + j * 8 + cbase + (e & 1);
                        int grow = wrow + r0 + 8 * (e >> 1);
                        float sv = cs[j][e] * 0.25f;
                        cs[j][e] = (gcol > grow) ? -1e30f : sv;
                    }
            } else {
#pragma unroll
                for (int j = 0; j < 8; j++)
#pragma unroll
                    for (int e = 0; e < 4; e++) cs[j][e] *= 0.25f;
            }

            // ---- online softmax ----
#pragma unroll
            for (int half = 0; half < 2; half++) {
                float mx = -1e30f;
#pragma unroll
                for (int j = 0; j < 8; j++)
                    mx = fmaxf(mx, fmaxf(cs[j][2 * half], cs[j][2 * half + 1]));
                mx = fmaxf(mx, __shfl_xor_sync(0xffffffffu, mx, 1));
                mx = fmaxf(mx, __shfl_xor_sync(0xffffffffu, mx, 2));
                float mn = fmaxf(mi[half], mx);
                float alpha = fast_exp(mi[half] - mn);
                mi[half] = mn;
                float rs = 0.0f;
#pragma unroll
                for (int j = 0; j < 8; j++) {
                    float p0 = fast_exp(cs[j][2 * half]     - mn);
                    float p1 = fast_exp(cs[j][2 * half + 1] - mn);
                    cs[j][2 * half] = p0;
                    cs[j][2 * half + 1] = p1;
                    rs += p0 + p1;
                }
                rs += __shfl_xor_sync(0xffffffffu, rs, 1);
                rs += __shfl_xor_sync(0xffffffffu, rs, 2);
                li[half] = li[half] * alpha + rs;
#pragma unroll
                for (int j = 0; j < 8; j++) {
                    co[j][2 * half]     *= alpha;
                    co[j][2 * half + 1] *= alpha;
                }
            }

            // ---- pack P (hi/lo) ----
            uint32_t pfh[4][4], pfl[4][4];
#pragma unroll
            for (int t = 0; t < 4; t++)
#pragma unroll
                for (int sub = 0; sub < 2; sub++) {
                    int j = 2 * t + sub;
                    split_pair(cs[j][0], cs[j][1],
                               pfh[t][sub * 2 + 0], pfl[t][sub * 2 + 0]);
                    split_pair(cs[j][2], cs[j][3],
                               pfh[t][sub * 2 + 1], pfl[t][sub * 2 + 1]);
                }

            // ---- O += (Ph+Pl) Vh : fragment-batched ----
#pragma unroll
            for (int t = 0; t < 4; t++) {
                uint32_t vf[4][4];
                int rowv = t * 16 + (lane & 7) + ((lane >> 3) & 1) * 8;
#pragma unroll
                for (int np = 0; np < 4; np++) {
                    int colv = np * 16 + ((lane >> 4) << 3);
                    LDMX4T(vf[np], bVh + rowv * ASTRIDE + colv * 2);
                }
#pragma unroll
                for (int np = 0; np < 4; np++) {
                    MMA_F16(co[2 * np],     pfh[t], vf[np]);
                    MMA_F16(co[2 * np + 1], pfh[t], vf[np] + 2);
                }
#pragma unroll
                for (int np = 0; np < 4; np++) {
                    MMA_F16(co[2 * np],     pfl[t], vf[np]);
                    MMA_F16(co[2 * np + 1], pfl[t], vf[np] + 2);
                }
            }
        }
        __syncthreads();
    };

    const uint32_t st0 = sStg;
    const uint32_t st1 = sStg + 2 * ABYTES;
    for (int kt = 0; kt < ntiles; kt += 2) {
        tile_body(kt,     st0, st1);
        tile_body(kt + 1, st1, st0);
    }

    // ---- epilogue: normalize, write hi-only A layout for proj ----
    float inv0 = 1.0f / li[0], inv1 = 1.0f / li[1];
#pragma unroll
    for (int j = 0; j < 8; j++) {
#pragma unroll
        for (int half = 0; half < 2; half++) {
            float inv = half ? inv1 : inv0;
            int row = (w << 4) + r0 + 8 * half;
            int m = b * TT + q0 + row;
            int Pidx = h * 32 + j * 4 + (lane & 3);
            *(uint32_t*)(atts + (size_t)m * 2048 + pairoffA(Pidx)) =
                pack2h(co[j][2 * half] * inv, co[j][2 * half + 1] * inv);
        }
    }
}

// ---------------------------------------------------------------------------
extern "C" void kernel_launch(void* const* d_in, const int* in_sizes, int n_in,
                              void* d_out, int out_size)
{
    const float* x      = (const float*)d_in[0];
    const float* w_attn = (const float*)d_in[1];
    const float* b_attn = (const float*)d_in[2];
    const float* w_proj = (const float*)d_in[3];
    const float* b_proj = (const float*)d_in[4];

    float* out = (float*)d_out;
    float* a_out = out;
    float* present = out + (size_t)M_TOT * DD;

    unsigned char *xs, *bta, *btp, *atts;
    __half *qsp, *ksp, *vsp;
    cudaGetSymbolAddress((void**)&xs,   g_xs);
    cudaGetSymbolAddress((void**)&bta,  g_bta);
    cudaGetSymbolAddress((void**)&btp,  g_btp);
    cudaGetSymbolAddress((void**)&atts, g_atts);
    cudaGetSymbolAddress((void**)&qsp,  g_qs);
    cudaGetSymbolAddress((void**)&ksp,  g_ks);
    cudaGetSymbolAddress((void**)&vsp,  g_vs);

    cudaFuncSetAttribute(f16_gemm_kernel,
                         cudaFuncAttributeMaxDynamicSharedMemorySize, GSMEM);
    cudaFuncSetAttribute(attn_mma_kernel,
                         cudaFuncAttributeMaxDynamicSharedMemorySize, ATT_SMEM);

    // Prepasses
    split_kernel<<<(M_TOT * DD / 4 + 255) / 256, 256>>>(
        (const float4*)x, xs, M_TOT * DD / 4);
    transpose_split_kernel<<<dim3(3 * DD / 32, DD / 32), dim3(32, 8)>>>(
        w_attn, bta, DD, 3 * DD);
    transpose_split_kernel<<<dim3(DD / 32, DD / 32), dim3(32, 8)>>>(
        w_proj, btp, DD, DD);

    // QKV GEMM (2-term) -> q/k/v hi planes + fp32 present
    f16_gemm_kernel<<<dim3(3 * DD / 128, M_TOT / 128), 256, GSMEM>>>(
        xs, bta, b_attn, nullptr, qsp, ksp, vsp, present, 3 * DD, 0);

    // Tensor-core flash attention -> g_atts (hi-only)
    attn_mma_kernel<<<dim3(TT / 128, HH, BB), 256, ATT_SMEM>>>(
        qsp, ksp, vsp, atts);

    // Projection GEMM (2-term) -> a_out
    f16_gemm_kernel<<<dim3(DD / 128, M_TOT / 128), 256, GSMEM>>>(
        atts, btp, b_proj, a_out, nullptr, nullptr, nullptr, nullptr, DD, 1);
}

// round 14
// speedup vs baseline: 1.1708x; 1.0538x over previous
#include <cuda_runtime.h>
#include <cuda_fp16.h>
#include <cstdint>

// Problem constants
#define BB 2
#define TT 2048
#define DD 1024
#define HH 16
#define DHH 64
#define M_TOT (BB*TT)                 // 4096
#define PRESENT_HALF (BB*HH*TT*DHH)   // 4194304
#define PLANE ((size_t)BB*HH*TT*DHH)  // elements per plane
#define GK 1024                       // GEMM K (compile-time)
#define NCH 64                        // GK/16 chunks

// ---------------------------------------------------------------------------
// Device-global scratch.
// B-operand layout (weights, hi+lo interleaved): row [K], K/16 chunks of 64B,
//   chunk = pairs [p0,p4,p1,p5,p2,p6,p3,p7], pair = 8B [hi2|lo2] fp16.
// A-operand layout (x, attn-out; hi only): row [K], K/16 chunks of 32B.
// Attention planes: Q/K/V all hi-only. [B][H][T][64] fp16.
// ---------------------------------------------------------------------------
__device__ unsigned char g_xs[(size_t)M_TOT * DD * 2];
__device__ unsigned char g_bta[(size_t)3 * DD * DD * 4];
__device__ unsigned char g_btp[(size_t)DD * DD * 4];
__device__ __half g_qs[PLANE];
__device__ __half g_ks[PLANE];
__device__ __half g_vs[PLANE];
__device__ unsigned char g_atts[(size_t)M_TOT * DD * 2];

// ---------------------------------------------------------------------------
// Helpers
// ---------------------------------------------------------------------------
__device__ __forceinline__ uint32_t smem_to_u32(const void* smem_ptr) {
    uint32_t addr;
    asm("{ .reg .u64 tmp; cvta.to.shared.u64 tmp, %1; cvt.u32.u64 %0, tmp; }"
        : "=r"(addr) : "l"(smem_ptr));
    return addr;
}

__device__ __forceinline__ uint32_t pack2h(float a, float b) {
    __half2 h = __floats2half2_rn(a, b);
    return *reinterpret_cast<uint32_t*>(&h);
}

__device__ __forceinline__ void split_pair(float a, float b,
                                           uint32_t& wh, uint32_t& wl) {
    __half ha = __float2half_rn(a);
    __half hb = __float2half_rn(b);
    float la = a - __half2float(ha);
    float lb = b - __half2float(hb);
    __half2 h = __halves2half2(ha, hb);
    __half2 l = __floats2half2_rn(la, lb);
    wh = *reinterpret_cast<uint32_t*>(&h);
    wl = *reinterpret_cast<uint32_t*>(&l);
}

__device__ __forceinline__ int pairoffB(int P) {
    int ch = P >> 3, p = P & 7;
    return ch * 64 + (p & 3) * 16 + (p >> 2) * 8;
}
__device__ __forceinline__ int pairoffA(int P) {
    int ch = P >> 3, p = P & 7;
    return ch * 32 + (p & 3) * 8 + (p >> 2) * 4;
}

__device__ __forceinline__ float fast_exp(float x) {
    x = fmaxf(x, -87.0f);
    float t = fmaf(x, 1.4426950408889634f, 12582912.0f);
    int   ni = __float_as_int(t);
    float n = t - 12582912.0f;
    float f = fmaf(x, 1.4426950408889634f, -n);
    float p = 1.3333558146e-3f;
    p = fmaf(p, f, 9.6181291076e-3f);
    p = fmaf(p, f, 5.5504108665e-2f);
    p = fmaf(p, f, 2.4022650696e-1f);
    p = fmaf(p, f, 6.9314718056e-1f);
    p = fmaf(p, f, 1.0f);
    return __int_as_float(__float_as_int(p) + (int)((unsigned)ni << 23));
}

#define CP16(s, g) \
    asm volatile("cp.async.cg.shared.global [%0], [%1], 16;" :: "r"(s), "l"(g))
#define CP_COMMIT() asm volatile("cp.async.commit_group;" ::: "memory")
#define CP_WAIT1()  asm volatile("cp.async.wait_group 1;" ::: "memory")
#define CP_WAIT2()  asm volatile("cp.async.wait_group 2;" ::: "memory")

#define MMA_F16(c, a, b) \
    asm volatile("mma.sync.aligned.m16n8k16.row.col.f32.f16.f16.f32 " \
        "{%0,%1,%2,%3},{%4,%5,%6,%7},{%8,%9},{%0,%1,%2,%3};" \
        : "+f"((c)[0]), "+f"((c)[1]), "+f"((c)[2]), "+f"((c)[3]) \
        : "r"((a)[0]), "r"((a)[1]), "r"((a)[2]), "r"((a)[3]), \
          "r"((b)[0]), "r"((b)[1]))

#define LDMX4(R, addr) \
    asm volatile("ldmatrix.sync.aligned.m8n8.x4.shared.b16 {%0,%1,%2,%3}, [%4];" \
        : "=r"((R)[0]), "=r"((R)[1]), "=r"((R)[2]), "=r"((R)[3]) : "r"(addr))

#define LDMX4T(R, addr) \
    asm volatile("ldmatrix.sync.aligned.m8n8.x4.trans.shared.b16 {%0,%1,%2,%3}, [%4];" \
        : "=r"((R)[0]), "=r"((R)[1]), "=r"((R)[2]), "=r"((R)[3]) : "r"(addr))

// ---------------------------------------------------------------------------
// Prepass 1: x -> hi-only interleaved A layout
// ---------------------------------------------------------------------------
__global__ void split_kernel(const float4* __restrict__ src,
                             unsigned char* __restrict__ dst, int n4)
{
    int i = blockIdx.x * blockDim.x + threadIdx.x;
    if (i < n4) {
        float4 v = src[i];
        int e = 4 * i;
        int row = e >> 10;
        int P0 = (e & 1023) >> 1;
        unsigned char* base = dst + (size_t)row * 2048;
        *(uint32_t*)(base + pairoffA(P0))     = pack2h(v.x, v.y);
        *(uint32_t*)(base + pairoffA(P0 + 1)) = pack2h(v.z, v.w);
    }
}

// ---------------------------------------------------------------------------
// Prepass 2: W[K,N] -> Bt[N][K] interleaved packed-split (hi+lo)
// ---------------------------------------------------------------------------
__global__ void transpose_split_kernel(const float* __restrict__ w,
                                       unsigned char* __restrict__ bt,
                                       int Kd, int Nd)
{
    __shared__ float t[32][33];
    int n0 = blockIdx.x * 32, k0 = blockIdx.y * 32;
    int tx = threadIdx.x, ty = threadIdx.y;
#pragma unroll
    for (int i = 0; i < 32; i += 8)
        t[ty + i][tx] = w[(size_t)(k0 + ty + i) * Nd + n0 + tx];
    __syncthreads();
    int tid = ty * 32 + tx;
    int po = tid & 15;
    int nl = tid >> 4;
#pragma unroll
    for (int half = 0; half < 2; half++) {
        int n_loc = nl + half * 16;
        float v0 = t[2 * po][n_loc];
        float v1 = t[2 * po + 1][n_loc];
        uint2 o;
        split_pair(v0, v1, o.x, o.y);
        *(uint2*)(bt + (size_t)(n0 + n_loc) * Kd * 4
                     + pairoffB((k0 >> 1) + po)) = o;
    }
}

// ---------------------------------------------------------------------------
// fp16 2-term mma.sync GEMM: C = Ahi @ (Bhi+Blo)^T + bias.  (R11 config.)
// CTA 128x128, 256 thr, chunk 16k, 4-stage, unroll 4.
// ---------------------------------------------------------------------------
#define GSTAGE 12288
#define GSMEM  (4 * GSTAGE)

__global__ __launch_bounds__(256, 2) void f16_gemm_kernel(
    const unsigned char* __restrict__ Ag, const unsigned char* __restrict__ Bg,
    const float* __restrict__ bias,
    float* __restrict__ Cout,
    __half* __restrict__ qsp, __half* __restrict__ ksp,
    __half* __restrict__ vsp,
    float* __restrict__ present, int N, int mode)
{
    extern __shared__ char smem[];
    const uint32_t smem_u = smem_to_u32(smem);
    const int tid = threadIdx.x;
    const int lane = tid & 31, wid = tid >> 5;
    const int wm = wid & 1, wn = wid >> 1;
    const int rowBase = blockIdx.y * 128, colBase = blockIdx.x * 128;

    const int ldr = tid >> 1;
    const unsigned char* gA = Ag + (size_t)(rowBase + ldr) * (GK * 2)
                                 + (tid & 1) * 16;
    const unsigned char* gB = Bg + (size_t)(colBase + ldr) * (GK * 4)
                                 + (tid & 1) * 32;
    const uint32_t sA = smem_u + ldr * 32 + (tid & 1) * 16;
    const uint32_t sB = smem_u + 4096 + ldr * 64 + (tid & 1) * 32;

#define LOAD_STAGE(chunk, stg) do {                        \
        uint32_t so = (uint32_t)(stg) * GSTAGE;            \
        CP16(sA + so,      gA + (size_t)(chunk) * 32);     \
        CP16(sB + so,      gB + (size_t)(chunk) * 64);     \
        CP16(sB + so + 16, gB + (size_t)(chunk) * 64 + 16);\
    } while (0)

    float c[4][4][4];
#pragma unroll
    for (int i = 0; i < 4; i++)
#pragma unroll
        for (int j = 0; j < 4; j++)
#pragma unroll
            for (int r = 0; r < 4; r++) c[i][j][r] = 0.0f;

    LOAD_STAGE(0, 0); CP_COMMIT();
    LOAD_STAGE(1, 1); CP_COMMIT();
    LOAD_STAGE(2, 2); CP_COMMIT();

    // per-thread invariant smem offsets
    const uint32_t aoff = (uint32_t)((wm * 64 + (lane >> 2)) * 32
                                     + (lane & 3) * 8);
    const uint32_t boff = (uint32_t)(4096 + (wn * 32 + (lane >> 2)) * 64
                                     + (lane & 3) * 16);

    const char* smem_c = smem;
#pragma unroll 4
    for (int ch = 0; ch < NCH; ch++) {
        CP_WAIT2();
        __syncthreads();
        const uint32_t sbase = (uint32_t)((ch & 3) * GSTAGE);

        uint32_t ah[4][4];
#pragma unroll
        for (int mf = 0; mf < 4; mf++) {
            const char* p = smem_c + aoff + sbase + mf * 512;
            uint2 t0 = *(const uint2*)(p);
            uint2 t1 = *(const uint2*)(p + 256);
            ah[mf][0] = t0.x; ah[mf][2] = t0.y;
            ah[mf][1] = t1.x; ah[mf][3] = t1.y;
        }
        uint32_t bh[4][2], bl[4][2];
#pragma unroll
        for (int nf = 0; nf < 4; nf++) {
            uint4 V = *(const uint4*)(smem_c + boff + sbase + nf * 512);
            bh[nf][0] = V.x; bl[nf][0] = V.y;
            bh[nf][1] = V.z; bl[nf][1] = V.w;
        }
        // term-major: accumulator revisit distance = 16 MMAs
#pragma unroll
        for (int mf = 0; mf < 4; mf++)
#pragma unroll
            for (int nf = 0; nf < 4; nf++)
                MMA_F16(c[mf][nf], ah[mf], bh[nf]);
#pragma unroll
        for (int mf = 0; mf < 4; mf++)
#pragma unroll
            for (int nf = 0; nf < 4; nf++)
                MMA_F16(c[mf][nf], ah[mf], bl[nf]);
        __syncthreads();
        if (ch + 3 < NCH) LOAD_STAGE(ch + 3, (ch + 3) & 3);
        CP_COMMIT();
    }

    // Epilogue
#pragma unroll
    for (int mf = 0; mf < 4; mf++) {
#pragma unroll
        for (int nf = 0; nf < 4; nf++) {
            int m0 = rowBase + wm * 64 + mf * 16 + (lane >> 2);
            int n  = colBase + wn * 32 + nf * 8 + (lane & 3) * 2;
            float b0 = bias[n], b1 = bias[n + 1];
#pragma unroll
            for (int half = 0; half < 2; half++) {
                int m = m0 + half * 8;
                float2 v;
                v.x = c[mf][nf][half * 2 + 0] + b0;
                v.y = c[mf][nf][half * 2 + 1] + b1;
                if (mode == 1) {
                    *(float2*)&Cout[(size_t)m * N + n] = v;
                } else {
                    int seg = n >> 10, nn = n & 1023;
                    int hh = nn >> 6, d = nn & 63;
                    int bb = m >> 11, t = m & 2047;
                    size_t idx = (((size_t)(bb * HH + hh)) * TT + t) * DHH + d;
                    if (seg == 0) {
                        *(uint32_t*)&qsp[idx] = pack2h(v.x, v.y);
                    } else if (seg == 1) {
                        *(float2*)&present[idx] = v;
                        *(uint32_t*)&ksp[idx] = pack2h(v.x, v.y);
                    } else {
                        *(float2*)&present[PRESENT_HALF + idx] = v;
                        *(uint32_t*)&vsp[idx] = pack2h(v.x, v.y);
                    }
                }
            }
        }
    }
}

// ---------------------------------------------------------------------------
// Flash attention on tensor cores (fp16).
// S = Qh Kh^T (1-term), O += Ph Vh (1-term).
// Block: 128 q-rows x 64 k-cols, 8 warps, reversed qt. kt loop manually
// unrolled x2 so stage addressing constant-folds (ntiles always even).
// ---------------------------------------------------------------------------
#define ASTRIDE 144
#define ABYTES  (64 * ASTRIDE)
#define QBYTES  (128 * ASTRIDE)
#define ATT_SMEM (QBYTES + 2 * 2 * ABYTES)   // 55296

__device__ __forceinline__ void att_load_stage(
    uint32_t dst, const __half* kh_g, const __half* vh_g, int k0, int tid)
{
    int r = tid >> 2;
    int qo = (tid & 3) * 32;
    const char* skh = (const char*)(kh_g + (size_t)(k0 + r) * DHH) + qo;
    const char* svh = (const char*)(vh_g + (size_t)(k0 + r) * DHH) + qo;
    uint32_t d0 = dst + r * ASTRIDE + qo;
#pragma unroll
    for (int i = 0; i < 2; i++) {
        CP16(d0 + i * 16,          skh + i * 16);
        CP16(d0 + ABYTES + i * 16, svh + i * 16);
    }
}

__global__ __launch_bounds__(256) void attn_mma_kernel(
    const __half* __restrict__ qs, const __half* __restrict__ ks,
    const __half* __restrict__ vs, unsigned char* __restrict__ atts)
{
    extern __shared__ char sm[];
    const uint32_t su = smem_to_u32(sm);
    const int tid = threadIdx.x, lane = tid & 31, w = tid >> 5;
    const int qt = gridDim.x - 1 - blockIdx.x;
    const int h = blockIdx.y, b = blockIdx.z;
    const int q0 = qt * 128;
    const size_t headoff = ((size_t)(b * HH + h)) * TT * DHH;

    const uint32_t sQh = su;
    const uint32_t sStg = su + QBYTES;

    const __half* qh_g = qs + headoff;
    const __half* kh_g = ks + headoff;
    const __half* vh_g = vs + headoff;

    // preload Q (hi, 128 rows) + stage 0
    {
        int r = tid >> 1;
        int cb = (tid & 1) * 64;
        const char* sh = (const char*)(qh_g + (size_t)(q0 + r) * DHH) + cb;
        uint32_t dh_ = sQh + r * ASTRIDE + cb;
#pragma unroll
        for (int i = 0; i < 4; i++)
            CP16(dh_ + i * 16, sh + i * 16);
        att_load_stage(sStg, kh_g, vh_g, 0, tid);
    }
    CP_COMMIT();

    uint32_t qfh[4][4];
    float co[8][4];
#pragma unroll
    for (int j = 0; j < 8; j++)
#pragma unroll
        for (int e = 0; e < 4; e++) co[j][e] = 0.0f;
    float mi[2] = {-1e30f, -1e30f}, li[2] = {0.0f, 0.0f};

    const int r0 = lane >> 2;
    const int cbase = 2 * (lane & 3);
    const int ntiles = 2 * qt + 2;   // always even
    const int wrow = q0 + (w << 4);

    auto tile_body = [&](int kt, uint32_t bKh, uint32_t ldst) {
        const int k0 = kt * 64;
        if (kt + 1 < ntiles)
            att_load_stage(ldst, kh_g, vh_g, (kt + 1) * 64, tid);
        CP_COMMIT();
        CP_WAIT1();
        __syncthreads();

        if (kt == 0) {
            int row = (w << 4) + (lane & 15);
            int colb = ((lane >> 4) << 3);
#pragma unroll
            for (int t = 0; t < 4; t++)
                LDMX4(qfh[t], sQh + row * ASTRIDE + (t * 16 + colb) * 2);
        }

        const bool active = (k0 <= wrow + 15);
        if (active) {
            const uint32_t bVh = bKh + ABYTES;

            // ---- S = Qh Kh^T (1-term), fragment-batched ----
            float cs[8][4];
#pragma unroll
            for (int j = 0; j < 8; j++)
#pragma unroll
                for (int e = 0; e < 4; e++) cs[j][e] = 0.0f;

#pragma unroll
            for (int u = 0; u < 2; u++) {
                uint32_t kf[8][4];
                int cola = u * 32 + ((lane >> 3) << 3);
#pragma unroll
                for (int j = 0; j < 8; j++) {
                    int rowa = j * 8 + (lane & 7);
                    LDMX4(kf[j], bKh + rowa * ASTRIDE + cola * 2);
                }
#pragma unroll
                for (int j = 0; j < 8; j++) MMA_F16(cs[j], qfh[2 * u], kf[j]);
#pragma unroll
                for (int j = 0; j < 8; j++) MMA_F16(cs[j], qfh[2 * u + 1], kf[j] + 2);
            }

            // ---- scale + causal mask ----
            if (k0 + 63 >= wrow) {
#pragma unroll
                for (int j = 0; j < 8; j++)
#pragma unroll
                    for (int e = 0; e < 4; e++) {
                        int gcol = k0 + j * 8 + cbase + (e & 1);
                        int grow = wrow + r0 + 8 * (e >> 1);
                        float sv = cs[j][e] * 0.25f;
                        cs[j][e] = (gcol > grow) ? -1e30f : sv;
                    }
            } else {
#pragma unroll
                for (int j = 0; j < 8; j++)
#pragma unroll
                    for (int e = 0; e < 4; e++) cs[j][e] *= 0.25f;
            }

            // ---- online softmax ----
#pragma unroll
            for (int half = 0; half < 2; half++) {
                float mx = -1e30f;
#pragma unroll
                for (int j = 0; j < 8; j++)
                    mx = fmaxf(mx, fmaxf(cs[j][2 * half], cs[j][2 * half + 1]));
                mx = fmaxf(mx, __shfl_xor_sync(0xffffffffu, mx, 1));
                mx = fmaxf(mx, __shfl_xor_sync(0xffffffffu, mx, 2));
                float mn = fmaxf(mi[half], mx);
                float alpha = fast_exp(mi[half] - mn);
                mi[half] = mn;
                float rs = 0.0f;
#pragma unroll
                for (int j = 0; j < 8; j++) {
                    float p0 = fast_exp(cs[j][2 * half]     - mn);
                    float p1 = fast_exp(cs[j][2 * half + 1] - mn);
                    cs[j][2 * half] = p0;
                    cs[j][2 * half + 1] = p1;
                    rs += p0 + p1;
                }
                rs += __shfl_xor_sync(0xffffffffu, rs, 1);
                rs += __shfl_xor_sync(0xffffffffu, rs, 2);
                li[half] = li[half] * alpha + rs;
#pragma unroll
                for (int j = 0; j < 8; j++) {
                    co[j][2 * half]     *= alpha;
                    co[j][2 * half + 1] *= alpha;
                }
            }

            // ---- pack P (hi only) ----
            uint32_t pfh[4][4];
#pragma unroll
            for (int t = 0; t < 4; t++)
#pragma unroll
                for (int sub = 0; sub < 2; sub++) {
                    int j = 2 * t + sub;
                    pfh[t][sub * 2 + 0] = pack2h(cs[j][0], cs[j][1]);
                    pfh[t][sub * 2 + 1] = pack2h(cs[j][2], cs[j][3]);
                }

            // ---- O += Ph Vh : fragment-batched ----
#pragma unroll
            for (int t = 0; t < 4; t++) {
                uint32_t vf[4][4];
                int rowv = t * 16 + (lane & 7) + ((lane >> 3) & 1) * 8;
#pragma unroll
                for (int np = 0; np < 4; np++) {
                    int colv = np * 16 + ((lane >> 4) << 3);
                    LDMX4T(vf[np], bVh + rowv * ASTRIDE + colv * 2);
                }
#pragma unroll
                for (int np = 0; np < 4; np++) {
                    MMA_F16(co[2 * np],     pfh[t], vf[np]);
                    MMA_F16(co[2 * np + 1], pfh[t], vf[np] + 2);
                }
            }
        }
        __syncthreads();
    };

    const uint32_t st0 = sStg;
    const uint32_t st1 = sStg + 2 * ABYTES;
    for (int kt = 0; kt < ntiles; kt += 2) {
        tile_body(kt,     st0, st1);
        tile_body(kt + 1, st1, st0);
    }

    // ---- epilogue: normalize, write hi-only A layout for proj ----
    float inv0 = 1.0f / li[0], inv1 = 1.0f / li[1];
#pragma unroll
    for (int j = 0; j < 8; j++) {
#pragma unroll
        for (int half = 0; half < 2; half++) {
            float inv = half ? inv1 : inv0;
            int row = (w << 4) + r0 + 8 * half;
            int m = b * TT + q0 + row;
            int Pidx = h * 32 + j * 4 + (lane & 3);
            *(uint32_t*)(atts + (size_t)m * 2048 + pairoffA(Pidx)) =
                pack2h(co[j][2 * half] * inv, co[j][2 * half + 1] * inv);
        }
    }
}

// ---------------------------------------------------------------------------
extern "C" void kernel_launch(void* const* d_in, const int* in_sizes, int n_in,
                              void* d_out, int out_size)
{
    const float* x      = (const float*)d_in[0];
    const float* w_attn = (const float*)d_in[1];
    const float* b_attn = (const float*)d_in[2];
    const float* w_proj = (const float*)d_in[3];
    const float* b_proj = (const float*)d_in[4];

    float* out = (float*)d_out;
    float* a_out = out;
    float* present = out + (size_t)M_TOT * DD;

    unsigned char *xs, *bta, *btp, *atts;
    __half *qsp, *ksp, *vsp;
    cudaGetSymbolAddress((void**)&xs,   g_xs);
    cudaGetSymbolAddress((void**)&bta,  g_bta);
    cudaGetSymbolAddress((void**)&btp,  g_btp);
    cudaGetSymbolAddress((void**)&atts, g_atts);
    cudaGetSymbolAddress((void**)&qsp,  g_qs);
    cudaGetSymbolAddress((void**)&ksp,  g_ks);
    cudaGetSymbolAddress((void**)&vsp,  g_vs);

    cudaFuncSetAttribute(f16_gemm_kernel,
                         cudaFuncAttributeMaxDynamicSharedMemorySize, GSMEM);
    cudaFuncSetAttribute(attn_mma_kernel,
                         cudaFuncAttributeMaxDynamicSharedMemorySize, ATT_SMEM);

    // Prepasses
    split_kernel<<<(M_TOT * DD / 4 + 255) / 256, 256>>>(
        (const float4*)x, xs, M_TOT * DD / 4);
    transpose_split_kernel<<<dim3(3 * DD / 32, DD / 32), dim3(32, 8)>>>(
        w_attn, bta, DD, 3 * DD);
    transpose_split_kernel<<<dim3(DD / 32, DD / 32), dim3(32, 8)>>>(
        w_proj, btp, DD, DD);

    // QKV GEMM (2-term) -> q/k/v hi planes + fp32 present
    f16_gemm_kernel<<<dim3(3 * DD / 128, M_TOT / 128), 256, GSMEM>>>(
        xs, bta, b_attn, nullptr, qsp, ksp, vsp, present, 3 * DD, 0);

    // Tensor-core flash attention -> g_atts (hi-only)
    attn_mma_kernel<<<dim3(TT / 128, HH, BB), 256, ATT_SMEM>>>(
        qsp, ksp, vsp, atts);

    // Projection GEMM (2-term) -> a_out
    f16_gemm_kernel<<<dim3(DD / 128, M_TOT / 128), 256, GSMEM>>>(
        atts, btp, b_proj, a_out, nullptr, nullptr, nullptr, nullptr, DD, 1);
}

// round 15
// speedup vs baseline: 1.5975x; 1.3645x over previous
#include <cuda_runtime.h>
#include <cuda_fp16.h>
#include <cstdint>

// Problem constants
#define BB 2
#define TT 2048
#define DD 1024
#define HH 16
#define DHH 64
#define M_TOT (BB*TT)                 // 4096
#define PRESENT_HALF (BB*HH*TT*DHH)   // 4194304
#define PLANE ((size_t)BB*HH*TT*DHH)  // elements per plane
#define GK 1024                       // GEMM K (compile-time)
#define NCH 64                        // GK/16 chunks

// ---------------------------------------------------------------------------
// Device-global scratch.
// Operand layout (both A and B, hi-only fp16): row [K], K/16 chunks of 32B,
//   chunk = pairs [p0,p4,p1,p5,p2,p6,p3,p7], pair = 4B [h(2k),h(2k+1)].
// Attention planes: Q/K/V hi-only, [B][H][T][64] fp16.
// ---------------------------------------------------------------------------
__device__ unsigned char g_xs[(size_t)M_TOT * DD * 2];
__device__ unsigned char g_bta[(size_t)3 * DD * DD * 2];
__device__ unsigned char g_btp[(size_t)DD * DD * 2];
__device__ __half g_qs[PLANE];
__device__ __half g_ks[PLANE];
__device__ __half g_vs[PLANE];
__device__ unsigned char g_atts[(size_t)M_TOT * DD * 2];

// ---------------------------------------------------------------------------
// Helpers
// ---------------------------------------------------------------------------
__device__ __forceinline__ uint32_t smem_to_u32(const void* smem_ptr) {
    uint32_t addr;
    asm("{ .reg .u64 tmp; cvta.to.shared.u64 tmp, %1; cvt.u32.u64 %0, tmp; }"
        : "=r"(addr) : "l"(smem_ptr));
    return addr;
}

__device__ __forceinline__ uint32_t pack2h(float a, float b) {
    __half2 h = __floats2half2_rn(a, b);
    return *reinterpret_cast<uint32_t*>(&h);
}

__device__ __forceinline__ int pairoffA(int P) {
    int ch = P >> 3, p = P & 7;
    return ch * 32 + (p & 3) * 8 + (p >> 2) * 4;
}

__device__ __forceinline__ float fast_exp(float x) {
    x = fmaxf(x, -87.0f);
    float t = fmaf(x, 1.4426950408889634f, 12582912.0f);
    int   ni = __float_as_int(t);
    float n = t - 12582912.0f;
    float f = fmaf(x, 1.4426950408889634f, -n);
    float p = 1.3333558146e-3f;
    p = fmaf(p, f, 9.6181291076e-3f);
    p = fmaf(p, f, 5.5504108665e-2f);
    p = fmaf(p, f, 2.4022650696e-1f);
    p = fmaf(p, f, 6.9314718056e-1f);
    p = fmaf(p, f, 1.0f);
    return __int_as_float(__float_as_int(p) + (int)((unsigned)ni << 23));
}

#define CP16(s, g) \
    asm volatile("cp.async.cg.shared.global [%0], [%1], 16;" :: "r"(s), "l"(g))
#define CP_COMMIT() asm volatile("cp.async.commit_group;" ::: "memory")
#define CP_WAIT1()  asm volatile("cp.async.wait_group 1;" ::: "memory")
#define CP_WAIT2()  asm volatile("cp.async.wait_group 2;" ::: "memory")

#define MMA_F16(c, a, b) \
    asm volatile("mma.sync.aligned.m16n8k16.row.col.f32.f16.f16.f32 " \
        "{%0,%1,%2,%3},{%4,%5,%6,%7},{%8,%9},{%0,%1,%2,%3};" \
        : "+f"((c)[0]), "+f"((c)[1]), "+f"((c)[2]), "+f"((c)[3]) \
        : "r"((a)[0]), "r"((a)[1]), "r"((a)[2]), "r"((a)[3]), \
          "r"((b)[0]), "r"((b)[1]))

#define LDMX4(R, addr) \
    asm volatile("ldmatrix.sync.aligned.m8n8.x4.shared.b16 {%0,%1,%2,%3}, [%4];" \
        : "=r"((R)[0]), "=r"((R)[1]), "=r"((R)[2]), "=r"((R)[3]) : "r"(addr))

#define LDMX4T(R, addr) \
    asm volatile("ldmatrix.sync.aligned.m8n8.x4.trans.shared.b16 {%0,%1,%2,%3}, [%4];" \
        : "=r"((R)[0]), "=r"((R)[1]), "=r"((R)[2]), "=r"((R)[3]) : "r"(addr))

// ---------------------------------------------------------------------------
// Prepass 1: x -> hi-only interleaved layout
// ---------------------------------------------------------------------------
__global__ void split_kernel(const float4* __restrict__ src,
                             unsigned char* __restrict__ dst, int n4)
{
    int i = blockIdx.x * blockDim.x + threadIdx.x;
    if (i < n4) {
        float4 v = src[i];
        int e = 4 * i;
        int row = e >> 10;
        int P0 = (e & 1023) >> 1;
        unsigned char* base = dst + (size_t)row * 2048;
        *(uint32_t*)(base + pairoffA(P0))     = pack2h(v.x, v.y);
        *(uint32_t*)(base + pairoffA(P0 + 1)) = pack2h(v.z, v.w);
    }
}

// ---------------------------------------------------------------------------
// Prepass 2: W[K,N] -> Bt[N][K] hi-only interleaved
// ---------------------------------------------------------------------------
__global__ void transpose_hi_kernel(const float* __restrict__ w,
                                    unsigned char* __restrict__ bt,
                                    int Kd, int Nd)
{
    __shared__ float t[32][33];
    int n0 = blockIdx.x * 32, k0 = blockIdx.y * 32;
    int tx = threadIdx.x, ty = threadIdx.y;
#pragma unroll
    for (int i = 0; i < 32; i += 8)
        t[ty + i][tx] = w[(size_t)(k0 + ty + i) * Nd + n0 + tx];
    __syncthreads();
    int tid = ty * 32 + tx;
    int po = tid & 15;
    int nl = tid >> 4;
#pragma unroll
    for (int half = 0; half < 2; half++) {
        int n_loc = nl + half * 16;
        float v0 = t[2 * po][n_loc];
        float v1 = t[2 * po + 1][n_loc];
        *(uint32_t*)(bt + (size_t)(n0 + n_loc) * Kd * 2
                        + pairoffA((k0 >> 1) + po)) = pack2h(v0, v1);
    }
}

// ---------------------------------------------------------------------------
// fp16 mma.sync GEMM: C = Ah @ Bh^T + bias.  K = GK (1024).
// CTA 128x128, 256 thr, chunk 16k, 4-stage (stage = A 4KB + B 4KB), unroll 4.
// mode 0: QKV -> q/k/v hi planes + fp32 present. mode 1: plain C.
// ---------------------------------------------------------------------------
#define GSTAGE 8192
#define GSMEM  (4 * GSTAGE)

__global__ __launch_bounds__(256, 2) void f16_gemm_kernel(
    const unsigned char* __restrict__ Ag, const unsigned char* __restrict__ Bg,
    const float* __restrict__ bias,
    float* __restrict__ Cout,
    __half* __restrict__ qsp, __half* __restrict__ ksp,
    __half* __restrict__ vsp,
    float* __restrict__ present, int N, int mode)
{
    extern __shared__ char smem[];
    const uint32_t smem_u = smem_to_u32(smem);
    const int tid = threadIdx.x;
    const int lane = tid & 31, wid = tid >> 5;
    const int wm = wid & 1, wn = wid >> 1;
    const int rowBase = blockIdx.y * 128, colBase = blockIdx.x * 128;

    const int ldr = tid >> 1;
    const unsigned char* gA = Ag + (size_t)(rowBase + ldr) * (GK * 2)
                                 + (tid & 1) * 16;
    const unsigned char* gB = Bg + (size_t)(colBase + ldr) * (GK * 2)
                                 + (tid & 1) * 16;
    const uint32_t sA = smem_u + ldr * 32 + (tid & 1) * 16;
    const uint32_t sB = smem_u + 4096 + ldr * 32 + (tid & 1) * 16;

#define LOAD_STAGE(chunk, stg) do {                        \
        uint32_t so = (uint32_t)(stg) * GSTAGE;            \
        CP16(sA + so, gA + (size_t)(chunk) * 32);          \
        CP16(sB + so, gB + (size_t)(chunk) * 32);          \
    } while (0)

    float c[4][4][4];
#pragma unroll
    for (int i = 0; i < 4; i++)
#pragma unroll
        for (int j = 0; j < 4; j++)
#pragma unroll
            for (int r = 0; r < 4; r++) c[i][j][r] = 0.0f;

    LOAD_STAGE(0, 0); CP_COMMIT();
    LOAD_STAGE(1, 1); CP_COMMIT();
    LOAD_STAGE(2, 2); CP_COMMIT();

    // per-thread invariant smem offsets
    const uint32_t aoff = (uint32_t)((wm * 64 + (lane >> 2)) * 32
                                     + (lane & 3) * 8);
    const uint32_t boff = (uint32_t)(4096 + (wn * 32 + (lane >> 2)) * 32
                                     + (lane & 3) * 8);

    const char* smem_c = smem;
#pragma unroll 4
    for (int ch = 0; ch < NCH; ch++) {
        CP_WAIT2();
        __syncthreads();
        const uint32_t sbase = (uint32_t)((ch & 3) * GSTAGE);

        uint32_t ah[4][4];
#pragma unroll
        for (int mf = 0; mf < 4; mf++) {
            const char* p = smem_c + aoff + sbase + mf * 512;
            uint2 t0 = *(const uint2*)(p);
            uint2 t1 = *(const uint2*)(p + 256);
            ah[mf][0] = t0.x; ah[mf][2] = t0.y;
            ah[mf][1] = t1.x; ah[mf][3] = t1.y;
        }
        uint32_t bh[4][2];
#pragma unroll
        for (int nf = 0; nf < 4; nf++) {
            uint2 V = *(const uint2*)(smem_c + boff + sbase + nf * 256);
            bh[nf][0] = V.x; bh[nf][1] = V.y;
        }
        // 16 MMAs, accumulator revisit distance = 16
#pragma unroll
        for (int mf = 0; mf < 4; mf++)
#pragma unroll
            for (int nf = 0; nf < 4; nf++)
                MMA_F16(c[mf][nf], ah[mf], bh[nf]);
        __syncthreads();
        if (ch + 3 < NCH) LOAD_STAGE(ch + 3, (ch + 3) & 3);
        CP_COMMIT();
    }

    // Epilogue
#pragma unroll
    for (int mf = 0; mf < 4; mf++) {
#pragma unroll
        for (int nf = 0; nf < 4; nf++) {
            int m0 = rowBase + wm * 64 + mf * 16 + (lane >> 2);
            int n  = colBase + wn * 32 + nf * 8 + (lane & 3) * 2;
            float b0 = bias[n], b1 = bias[n + 1];
#pragma unroll
            for (int half = 0; half < 2; half++) {
                int m = m0 + half * 8;
                float2 v;
                v.x = c[mf][nf][half * 2 + 0] + b0;
                v.y = c[mf][nf][half * 2 + 1] + b1;
                if (mode == 1) {
                    *(float2*)&Cout[(size_t)m * N + n] = v;
                } else {
                    int seg = n >> 10, nn = n & 1023;
                    int hh = nn >> 6, d = nn & 63;
                    int bb = m >> 11, t = m & 2047;
                    size_t idx = (((size_t)(bb * HH + hh)) * TT + t) * DHH + d;
                    if (seg == 0) {
                        *(uint32_t*)&qsp[idx] = pack2h(v.x, v.y);
                    } else if (seg == 1) {
                        *(float2*)&present[idx] = v;
                        *(uint32_t*)&ksp[idx] = pack2h(v.x, v.y);
                    } else {
                        *(float2*)&present[PRESENT_HALF + idx] = v;
                        *(uint32_t*)&vsp[idx] = pack2h(v.x, v.y);
                    }
                }
            }
        }
    }
}

// ---------------------------------------------------------------------------
// Flash attention on tensor cores (fp16, 1-term both GEMMs). Unchanged R14.
// Block: 128 q-rows x 64 k-cols, 8 warps, reversed qt, x2-unrolled kt loop.
// ---------------------------------------------------------------------------
#define ASTRIDE 144
#define ABYTES  (64 * ASTRIDE)
#define QBYTES  (128 * ASTRIDE)
#define ATT_SMEM (QBYTES + 2 * 2 * ABYTES)   // 55296

__device__ __forceinline__ void att_load_stage(
    uint32_t dst, const __half* kh_g, const __half* vh_g, int k0, int tid)
{
    int r = tid >> 2;
    int qo = (tid & 3) * 32;
    const char* skh = (const char*)(kh_g + (size_t)(k0 + r) * DHH) + qo;
    const char* svh = (const char*)(vh_g + (size_t)(k0 + r) * DHH) + qo;
    uint32_t d0 = dst + r * ASTRIDE + qo;
#pragma unroll
    for (int i = 0; i < 2; i++) {
        CP16(d0 + i * 16,          skh + i * 16);
        CP16(d0 + ABYTES + i * 16, svh + i * 16);
    }
}

__global__ __launch_bounds__(256) void attn_mma_kernel(
    const __half* __restrict__ qs, const __half* __restrict__ ks,
    const __half* __restrict__ vs, unsigned char* __restrict__ atts)
{
    extern __shared__ char sm[];
    const uint32_t su = smem_to_u32(sm);
    const int tid = threadIdx.x, lane = tid & 31, w = tid >> 5;
    const int qt = gridDim.x - 1 - blockIdx.x;
    const int h = blockIdx.y, b = blockIdx.z;
    const int q0 = qt * 128;
    const size_t headoff = ((size_t)(b * HH + h)) * TT * DHH;

    const uint32_t sQh = su;
    const uint32_t sStg = su + QBYTES;

    const __half* qh_g = qs + headoff;
    const __half* kh_g = ks + headoff;
    const __half* vh_g = vs + headoff;

    // preload Q (128 rows) + stage 0
    {
        int r = tid >> 1;
        int cb = (tid & 1) * 64;
        const char* sh = (const char*)(qh_g + (size_t)(q0 + r) * DHH) + cb;
        uint32_t dh_ = sQh + r * ASTRIDE + cb;
#pragma unroll
        for (int i = 0; i < 4; i++)
            CP16(dh_ + i * 16, sh + i * 16);
        att_load_stage(sStg, kh_g, vh_g, 0, tid);
    }
    CP_COMMIT();

    uint32_t qfh[4][4];
    float co[8][4];
#pragma unroll
    for (int j = 0; j < 8; j++)
#pragma unroll
        for (int e = 0; e < 4; e++) co[j][e] = 0.0f;
    float mi[2] = {-1e30f, -1e30f}, li[2] = {0.0f, 0.0f};

    const int r0 = lane >> 2;
    const int cbase = 2 * (lane & 3);
    const int ntiles = 2 * qt + 2;   // always even
    const int wrow = q0 + (w << 4);

    auto tile_body = [&](int kt, uint32_t bKh, uint32_t ldst) {
        const int k0 = kt * 64;
        if (kt + 1 < ntiles)
            att_load_stage(ldst, kh_g, vh_g, (kt + 1) * 64, tid);
        CP_COMMIT();
        CP_WAIT1();
        __syncthreads();

        if (kt == 0) {
            int row = (w << 4) + (lane & 15);
            int colb = ((lane >> 4) << 3);
#pragma unroll
            for (int t = 0; t < 4; t++)
                LDMX4(qfh[t], sQh + row * ASTRIDE + (t * 16 + colb) * 2);
        }

        const bool active = (k0 <= wrow + 15);
        if (active) {
            const uint32_t bVh = bKh + ABYTES;

            // ---- S = Qh Kh^T, fragment-batched ----
            float cs[8][4];
#pragma unroll
            for (int j = 0; j < 8; j++)
#pragma unroll
                for (int e = 0; e < 4; e++) cs[j][e] = 0.0f;

#pragma unroll
            for (int u = 0; u < 2; u++) {
                uint32_t kf[8][4];
                int cola = u * 32 + ((lane >> 3) << 3);
#pragma unroll
                for (int j = 0; j < 8; j++) {
                    int rowa = j * 8 + (lane & 7);
                    LDMX4(kf[j], bKh + rowa * ASTRIDE + cola * 2);
                }
#pragma unroll
                for (int j = 0; j < 8; j++) MMA_F16(cs[j], qfh[2 * u], kf[j]);
#pragma unroll
                for (int j = 0; j < 8; j++) MMA_F16(cs[j], qfh[2 * u + 1], kf[j] + 2);
            }

            // ---- scale + causal mask ----
            if (k0 + 63 >= wrow) {
#pragma unroll
                for (int j = 0; j < 8; j++)
#pragma unroll
                    for (int e = 0; e < 4; e++) {
                        int gcol = k0 + j * 8 + cbase + (e & 1);
                        int grow = wrow + r0 + 8 * (e >> 1);
                        float sv = cs[j][e] * 0.25f;
                        cs[j][e] = (gcol > grow) ? -1e30f : sv;
                    }
            } else {
#pragma unroll
                for (int j = 0; j < 8; j++)
#pragma unroll
                    for (int e = 0; e < 4; e++) cs[j][e] *= 0.25f;
            }

            // ---- online softmax ----
#pragma unroll
            for (int half = 0; half < 2; half++) {
                float mx = -1e30f;
#pragma unroll
                for (int j = 0; j < 8; j++)
                    mx = fmaxf(mx, fmaxf(cs[j][2 * half], cs[j][2 * half + 1]));
                mx = fmaxf(mx, __shfl_xor_sync(0xffffffffu, mx, 1));
                mx = fmaxf(mx, __shfl_xor_sync(0xffffffffu, mx, 2));
                float mn = fmaxf(mi[half], mx);
                float alpha = fast_exp(mi[half] - mn);
                mi[half] = mn;
                float rs = 0.0f;
#pragma unroll
                for (int j = 0; j < 8; j++) {
                    float p0 = fast_exp(cs[j][2 * half]     - mn);
                    float p1 = fast_exp(cs[j][2 * half + 1] - mn);
                    cs[j][2 * half] = p0;
                    cs[j][2 * half + 1] = p1;
                    rs += p0 + p1;
                }
                rs += __shfl_xor_sync(0xffffffffu, rs, 1);
                rs += __shfl_xor_sync(0xffffffffu, rs, 2);
                li[half] = li[half] * alpha + rs;
#pragma unroll
                for (int j = 0; j < 8; j++) {
                    co[j][2 * half]     *= alpha;
                    co[j][2 * half + 1] *= alpha;
                }
            }

            // ---- pack P (hi only) ----
            uint32_t pfh[4][4];
#pragma unroll
            for (int t = 0; t < 4; t++)
#pragma unroll
                for (int sub = 0; sub < 2; sub++) {
                    int j = 2 * t + sub;
                    pfh[t][sub * 2 + 0] = pack2h(cs[j][0], cs[j][1]);
                    pfh[t][sub * 2 + 1] = pack2h(cs[j][2], cs[j][3]);
                }

            // ---- O += Ph Vh : fragment-batched ----
#pragma unroll
            for (int t = 0; t < 4; t++) {
                uint32_t vf[4][4];
                int rowv = t * 16 + (lane & 7) + ((lane >> 3) & 1) * 8;
#pragma unroll
                for (int np = 0; np < 4; np++) {
                    int colv = np * 16 + ((lane >> 4) << 3);
                    LDMX4T(vf[np], bVh + rowv * ASTRIDE + colv * 2);
                }
#pragma unroll
                for (int np = 0; np < 4; np++) {
                    MMA_F16(co[2 * np],     pfh[t], vf[np]);
                    MMA_F16(co[2 * np + 1], pfh[t], vf[np] + 2);
                }
            }
        }
        __syncthreads();
    };

    const uint32_t st0 = sStg;
    const uint32_t st1 = sStg + 2 * ABYTES;
    for (int kt = 0; kt < ntiles; kt += 2) {
        tile_body(kt,     st0, st1);
        tile_body(kt + 1, st1, st0);
    }

    // ---- epilogue: normalize, write hi-only layout for proj ----
    float inv0 = 1.0f / li[0], inv1 = 1.0f / li[1];
#pragma unroll
    for (int j = 0; j < 8; j++) {
#pragma unroll
        for (int half = 0; half < 2; half++) {
            float inv = half ? inv1 : inv0;
            int row = (w << 4) + r0 + 8 * half;
            int m = b * TT + q0 + row;
            int Pidx = h * 32 + j * 4 + (lane & 3);
            *(uint32_t*)(atts + (size_t)m * 2048 + pairoffA(Pidx)) =
                pack2h(co[j][2 * half] * inv, co[j][2 * half + 1] * inv);
        }
    }
}

// ---------------------------------------------------------------------------
extern "C" void kernel_launch(void* const* d_in, const int* in_sizes, int n_in,
                              void* d_out, int out_size)
{
    const float* x      = (const float*)d_in[0];
    const float* w_attn = (const float*)d_in[1];
    const float* b_attn = (const float*)d_in[2];
    const float* w_proj = (const float*)d_in[3];
    const float* b_proj = (const float*)d_in[4];

    float* out = (float*)d_out;
    float* a_out = out;
    float* present = out + (size_t)M_TOT * DD;

    unsigned char *xs, *bta, *btp, *atts;
    __half *qsp, *ksp, *vsp;
    cudaGetSymbolAddress((void**)&xs,   g_xs);
    cudaGetSymbolAddress((void**)&bta,  g_bta);
    cudaGetSymbolAddress((void**)&btp,  g_btp);
    cudaGetSymbolAddress((void**)&atts, g_atts);
    cudaGetSymbolAddress((void**)&qsp,  g_qs);
    cudaGetSymbolAddress((void**)&ksp,  g_ks);
    cudaGetSymbolAddress((void**)&vsp,  g_vs);

    cudaFuncSetAttribute(f16_gemm_kernel,
                         cudaFuncAttributeMaxDynamicSharedMemorySize, GSMEM);
    cudaFuncSetAttribute(attn_mma_kernel,
                         cudaFuncAttributeMaxDynamicSharedMemorySize, ATT_SMEM);

    // Prepasses
    split_kernel<<<(M_TOT * DD / 4 + 255) / 256, 256>>>(
        (const float4*)x, xs, M_TOT * DD / 4);
    transpose_hi_kernel<<<dim3(3 * DD / 32, DD / 32), dim3(32, 8)>>>(
        w_attn, bta, DD, 3 * DD);
    transpose_hi_kernel<<<dim3(DD / 32, DD / 32), dim3(32, 8)>>>(
        w_proj, btp, DD, DD);

    // QKV GEMM -> q/k/v hi planes + fp32 present
    f16_gemm_kernel<<<dim3(3 * DD / 128, M_TOT / 128), 256, GSMEM>>>(
        xs, bta, b_attn, nullptr, qsp, ksp, vsp, present, 3 * DD, 0);

    // Tensor-core flash attention -> g_atts
    attn_mma_kernel<<<dim3(TT / 128, HH, BB), 256, ATT_SMEM>>>(
        qsp, ksp, vsp, atts);

    // Projection GEMM -> a_out
    f16_gemm_kernel<<<dim3(DD / 128, M_TOT / 128), 256, GSMEM>>>(
        atts, btp, b_proj, a_out, nullptr, nullptr, nullptr, nullptr, DD, 1);
}